// round 1
// baseline (speedup 1.0000x reference)
#include <cuda_runtime.h>
#include <math.h>

#define NB   16
#define HH   160
#define WW   160
#define HW   (HH*WW)
#define TOPK 32
#define CAP  5120
#define NV   68
#define RAD2DEG 57.29577951308232f

// ---- scratch (device globals; no allocations) ----
__device__ float g_peaks[NB*HW];
__device__ float g_scores[NB*TOPK];
__device__ int   g_idxs[NB*TOPK];
__device__ float g_lnmks[NB*TOPK*NV*2];
__device__ float g_bbox[NB*TOPK*5];
__device__ float g_pose[NB*TOPK*3];

// ============================================================
// Kernel 1: peak map (3x3 max-pool SAME) + exact per-batch top-32
// Tie-break: higher value first, then lower flat index (matches lax.top_k).
// Fast path: compact positive peaks to shared, 32 argmax rounds there.
// Fallback (cnt<32 or cnt>CAP): argmax rounds over full peak array.
// ============================================================
__global__ void __launch_bounds__(1024) topk_kernel(const float* __restrict__ hms) {
    int b   = blockIdx.x;
    int tid = threadIdx.x;
    const float* h = hms + (size_t)b * HW;
    float* pk = g_peaks + (size_t)b * HW;

    __shared__ float cv[CAP];
    __shared__ int   ci[CAP];
    __shared__ int   s_cnt;
    __shared__ float rv[32];
    __shared__ int   ri[32];
    __shared__ int   rp[32];

    if (tid == 0) s_cnt = 0;
    __syncthreads();

    // peaks + candidate compaction
    for (int i = tid; i < HW; i += 1024) {
        int y = i / WW, x = i - y * WW;
        float v = h[i];
        float m = v;
        int y0 = (y > 0)      ? y - 1 : y;
        int y1 = (y < HH - 1) ? y + 1 : y;
        int x0 = (x > 0)      ? x - 1 : x;
        int x1 = (x < WW - 1) ? x + 1 : x;
        for (int yy = y0; yy <= y1; yy++)
            for (int xx = x0; xx <= x1; xx++)
                m = fmaxf(m, h[yy * WW + xx]);
        float p = (v == m) ? v : 0.0f;
        pk[i] = p;
        if (p > 0.0f) {
            int pos = atomicAdd(&s_cnt, 1);
            if (pos < CAP) { cv[pos] = p; ci[pos] = i; }
        }
    }
    __syncthreads();

    int  cnt  = s_cnt;
    bool fast = (cnt >= TOPK) && (cnt <= CAP);
    int lane = tid & 31, wid = tid >> 5;

    for (int r = 0; r < TOPK; r++) {
        float bv = -2.0f; int bi = 0x3fffffff; int bp = -1;
        if (fast) {
            for (int i = tid; i < cnt; i += 1024) {
                float v = cv[i]; int ii = ci[i];
                if (v > bv || (v == bv && ii < bi)) { bv = v; bi = ii; bp = i; }
            }
        } else {
            for (int i = tid; i < HW; i += 1024) {
                float v = pk[i];
                if (v > bv || (v == bv && i < bi)) { bv = v; bi = i; bp = -1; }
            }
        }
        // warp reduce (val desc, idx asc)
        #pragma unroll
        for (int o = 16; o; o >>= 1) {
            float v2 = __shfl_down_sync(0xffffffffu, bv, o);
            int   i2 = __shfl_down_sync(0xffffffffu, bi, o);
            int   p2 = __shfl_down_sync(0xffffffffu, bp, o);
            if (v2 > bv || (v2 == bv && i2 < bi)) { bv = v2; bi = i2; bp = p2; }
        }
        if (lane == 0) { rv[wid] = bv; ri[wid] = bi; rp[wid] = bp; }
        __syncthreads();
        if (wid == 0) {
            bv = rv[lane]; bi = ri[lane]; bp = rp[lane];
            #pragma unroll
            for (int o = 16; o; o >>= 1) {
                float v2 = __shfl_down_sync(0xffffffffu, bv, o);
                int   i2 = __shfl_down_sync(0xffffffffu, bi, o);
                int   p2 = __shfl_down_sync(0xffffffffu, bp, o);
                if (v2 > bv || (v2 == bv && i2 < bi)) { bv = v2; bi = i2; bp = p2; }
            }
            if (lane == 0) {
                g_scores[b * TOPK + r] = bv;
                g_idxs[b * TOPK + r]   = bi;
                if (fast) cv[bp] = -1.0f;
                else      pk[bi] = -1.0f;
            }
        }
        __syncthreads();
    }
}

// ============================================================
// Kernel 2: per-detection geometry (512 blocks, one per detection)
// params gather+denorm -> verts = u + S*shp + E*exp -> landmark projection
// -> bbox (min/max) + pose
// ============================================================
__global__ void __launch_bounds__(256) geom_kernel(
    const float* __restrict__ pmaps,
    const float* __restrict__ oshapes,
    const float* __restrict__ pms,
    const float* __restrict__ u_base,
    const float* __restrict__ shp_base,
    const float* __restrict__ exp_base)
{
    int det = blockIdx.x;
    int b   = det >> 5;
    int tid = threadIdx.x;

    __shared__ float sp[91];
    __shared__ float sverts[204];
    __shared__ float syv[NV], sxv[NV];

    float score = g_scores[det];
    int   idx   = g_idxs[det];

    // gather + denorm: p = raw*std + mean
    for (int j = tid; j < 91; j += 256)
        sp[j] = fmaf(pmaps[((size_t)b * HW + (size_t)idx) * 91 + j], pms[91 + j], pms[j]);
    __syncthreads();

    // verts: 204 rows, 50+29 basis terms each
    if (tid < 204) {
        float a = u_base[tid];
        const float* sb = shp_base + (size_t)tid * 50;
        #pragma unroll
        for (int k = 0; k < 50; k++) a = fmaf(sb[k], sp[12 + k], a);
        const float* eb = exp_base + (size_t)tid * 29;
        #pragma unroll
        for (int k = 0; k < 29; k++) a = fmaf(eb[k], sp[62 + k], a);
        sverts[tid] = a;
    }
    __syncthreads();

    float s   = sp[0];
    float R00 = sp[1], R01 = sp[2],  R02 = sp[3];
    float R10 = sp[5], R11 = sp[6],  R12 = sp[7];

    int ys = idx / WW, xs = idx - (idx / WW) * WW;
    float ry  = oshapes[b * 2 + 0] / 160.0f;
    float rx  = oshapes[b * 2 + 1] / 160.0f;
    float coy = (float)ys * ry;
    float cox = (float)xs * rx;

    if (tid < NV) {
        float vx = sverts[3 * tid], vy = sverts[3 * tid + 1], vz = sverts[3 * tid + 2];
        float l0 = s * (vx * R00 + vy * R01 + vz * R02);
        float l1 = s * (vx * R10 + vy * R11 + vz * R12);
        float yx0 = l1 + coy;   // y
        float yx1 = l0 + cox;   // x
        g_lnmks[((size_t)det * NV + tid) * 2 + 0] = yx0;
        g_lnmks[((size_t)det * NV + tid) * 2 + 1] = yx1;
        syv[tid] = yx0; sxv[tid] = yx1;
    }
    __syncthreads();

    if (tid == 0) {
        float tly = syv[0], bry = syv[0], tlx = sxv[0], brx = sxv[0];
        for (int v = 1; v < NV; v++) {
            tly = fminf(tly, syv[v]); bry = fmaxf(bry, syv[v]);
            tlx = fminf(tlx, sxv[v]); brx = fmaxf(brx, sxv[v]);
        }
        bool mask = score > 0.5f;
        float* bb = g_bbox + (size_t)det * 5;
        if (mask) { bb[0] = tly; bb[1] = tlx; bb[2] = bry; bb[3] = brx; bb[4] = score; }
        else      { bb[0] = -1.0f; bb[1] = -1.0f; bb[2] = -1.0f; bb[3] = -1.0f; bb[4] = -1.0f; }

        // pose (faithful to reference: cos applied to yaw in DEGREES)
        float R20 = sp[9], R21 = sp[10], R22 = sp[11];
        float yaw   = asinf(-R20) * RAD2DEG;
        float cyw   = cosf(yaw);
        float pitch = atan2f(R21 / cyw, R22 / cyw) * RAD2DEG;
        float roll  = atan2f(R10 / cyw, R00 / cyw) * RAD2DEG;
        g_pose[(size_t)det * 3 + 0] = pitch;
        g_pose[(size_t)det * 3 + 1] = yaw;
        g_pose[(size_t)det * 3 + 2] = roll;
    }
}

// ============================================================
// Kernel 3: per-batch NMS (warp ballot, sequential greedy — order is
// identity since scores are already descending with -1 suffix),
// then all inf/-1/0 masking + output packing in tuple order.
// ============================================================
__global__ void __launch_bounds__(256) nms_kernel(float* __restrict__ out) {
    int b   = blockIdx.x;
    int tid = threadIdx.x;

    __shared__ float sbox[TOPK][4], sscore[TOPK];
    __shared__ float sob[TOPK][4],  sosc[TOPK];
    __shared__ int   svalid[TOPK],  smatch[TOPK];

    if (tid < TOPK) {
        const float* bb = g_bbox + ((size_t)b * TOPK + tid) * 5;
        #pragma unroll
        for (int c = 0; c < 4; c++) { sbox[tid][c] = bb[c]; sob[tid][c] = 0.0f; }
        sscore[tid] = bb[4];
        sosc[tid]   = 0.0f;
    }
    __syncthreads();

    if (tid < TOPK) {   // warp 0 does NMS
        int lane = tid;
        float b0 = sbox[lane][0], b1 = sbox[lane][1], b2 = sbox[lane][2], b3 = sbox[lane][3];
        float area = (b2 - b0) * (b3 - b1);
        unsigned supp = 0u;
        for (int i = 0; i < TOPK; i++) {
            if (!((supp >> i) & 1u)) {   // uniform across warp
                float i0 = sbox[i][0], i1 = sbox[i][1], i2 = sbox[i][2], i3 = sbox[i][3];
                float ia = (i2 - i0) * (i3 - i1);
                float yy = fminf(b2, i2) - fmaxf(b0, i0);
                float xx = fminf(b3, i3) - fmaxf(b1, i1);
                float inter = fmaxf(yy, 0.0f) * fmaxf(xx, 0.0f);
                float uni   = area + ia - inter;
                float iou   = inter / fmaxf(uni, 1e-8f);
                bool  sup   = (iou > 0.4f) && (lane > i);
                supp |= __ballot_sync(0xffffffffu, sup);
            }
        }
        bool keep = !((supp >> lane) & 1u);
        unsigned km = __ballot_sync(0xffffffffu, keep);
        int rank = __popc(km & ((1u << lane) - 1u));
        if (keep) {
            sob[rank][0] = b0; sob[rank][1] = b1; sob[rank][2] = b2; sob[rank][3] = b3;
            sosc[rank]   = sscore[lane];
        }
    }
    __syncthreads();

    const float INF = __int_as_float(0x7f800000);

    if (tid < TOPK) {   // -1 -> inf, 0 -> inf; det_valid
        bool valid = true;
        #pragma unroll
        for (int c = 0; c < 4; c++) {
            float v = sob[tid][c];
            if (v == -1.0f || v == 0.0f) { v = INF; valid = false; }
            sob[tid][c] = v;
        }
        svalid[tid] = valid ? 1 : 0;
    }
    __syncthreads();

    if (tid < TOPK) {   // matched[n]: original score appears among valid kept scores
        float sn = g_scores[b * TOPK + tid];
        int m = 0;
        for (int k = 0; k < TOPK; k++)
            if (svalid[k] && sosc[k] == sn) m = 1;
        smatch[tid] = m;
    }
    __syncthreads();

    // ---- out_bboxes (B,32,6) at offset 0 ----
    float* ob = out + (size_t)b * TOPK * 6;
    for (int e = tid; e < TOPK * 6; e += 256) {
        int k = e / 6, c = e - k * 6;
        float v = (c < 4) ? sob[k][c] : ((c == 4) ? sosc[k] : 0.0f);
        ob[e] = v;
    }
    // ---- out_lnmks (B,32,68,2) at offset NB*32*6 ----
    float* ol = out + (size_t)NB * TOPK * 6 + (size_t)b * TOPK * NV * 2;
    for (int e = tid; e < TOPK * NV * 2; e += 256) {
        int n = e / (NV * 2);
        float l = g_lnmks[(size_t)b * TOPK * NV * 2 + e];
        float v = (smatch[n] && l != -1.0f) ? l : INF;
        ol[e] = v;
    }
    // ---- out_pose (B,32,3) ----
    float* op = out + (size_t)NB * TOPK * 6 + (size_t)NB * TOPK * NV * 2 + (size_t)b * TOPK * 3;
    for (int e = tid; e < TOPK * 3; e += 256) {
        int n = e / 3;
        float p = g_pose[(size_t)b * TOPK * 3 + e];
        float v = (smatch[n] && p != -1.0f) ? p : INF;
        op[e] = v;
    }
}

extern "C" void kernel_launch(void* const* d_in, const int* in_sizes, int n_in,
                              void* d_out, int out_size) {
    const float* hms      = (const float*)d_in[0];
    const float* pmaps    = (const float*)d_in[1];
    const float* oshapes  = (const float*)d_in[2];
    const float* pms      = (const float*)d_in[3];
    const float* u_base   = (const float*)d_in[4];
    const float* shp_base = (const float*)d_in[5];
    const float* exp_base = (const float*)d_in[6];
    float* out = (float*)d_out;

    topk_kernel<<<NB, 1024>>>(hms);
    geom_kernel<<<NB * TOPK, 256>>>(pmaps, oshapes, pms, u_base, shp_base, exp_base);
    nms_kernel<<<NB, 256>>>(out);
}

// round 2
// speedup vs baseline: 1.4938x; 1.4938x over previous
#include <cuda_runtime.h>
#include <math.h>

#define NB   16
#define HH   160
#define WW   160
#define HW   (HH*WW)
#define TOPK 32
#define CAP  3584
#define NBINS 2048
#define MAXM 1024
#define NV   68
#define RAD2DEG 57.29577951308232f

// ---- scratch (device globals; no allocations) ----
__device__ float g_peaks[NB*HW];
__device__ float g_scores[NB*TOPK];
__device__ int   g_idxs[NB*TOPK];
__device__ float g_lnmks[NB*TOPK*NV*2];
__device__ float g_bbox[NB*TOPK*5];
__device__ float g_pose[NB*TOPK*3];

// ============================================================
// Kernel 1: 3x3 max-pool peaks (float4 vectorized) + exact top-32
// via histogram-select. Tie-break (value desc, index asc) exact via
// 64-bit keys. Fallback: block-wide argmax rounds over g_peaks.
// ============================================================
__global__ void __launch_bounds__(1024) topk_kernel(const float* __restrict__ hms) {
    int b   = blockIdx.x;
    int tid = threadIdx.x;
    int lane = tid & 31;
    const float* h = hms + (size_t)b * HW;
    float* pk = g_peaks + (size_t)b * HW;

    __shared__ float cv[CAP];
    __shared__ int   ci[CAP];
    __shared__ int   hist[NBINS];
    __shared__ unsigned long long keys[MAXM];
    __shared__ int   s_cnt, s_m, s_bstar, s_fast;
    __shared__ float s_sc[TOPK];
    __shared__ int   s_ix[TOPK];
    __shared__ float rv[32];
    __shared__ int   rid[32];

    if (tid == 0) { s_cnt = 0; s_m = 0; }
    for (int i = tid; i < NBINS; i += 1024) hist[i] = 0;
    __syncthreads();

    const float NEG = -1e30f;

    // ---- peaks + ballot-compacted candidates ----
    for (int c = tid; c < HW / 4; c += 1024) {
        int px = c * 4;
        int y  = px / WW;
        int x0 = px - y * WW;
        int ym = (y > 0)      ? y - 1 : y;
        int yp = (y < HH - 1) ? y + 1 : y;
        float4 a0 = *(const float4*)(h + (size_t)ym * WW + x0);
        float4 a1 = *(const float4*)(h + (size_t)y  * WW + x0);
        float4 a2 = *(const float4*)(h + (size_t)yp * WW + x0);
        float m0 = fmaxf(a1.x, fmaxf(a0.x, a2.x));
        float m1 = fmaxf(a1.y, fmaxf(a0.y, a2.y));
        float m2 = fmaxf(a1.z, fmaxf(a0.z, a2.z));
        float m3 = fmaxf(a1.w, fmaxf(a0.w, a2.w));
        float lm = NEG, rm = NEG;
        if (x0 > 0) {
            int xl = x0 - 1;
            lm = fmaxf(h[(size_t)y * WW + xl], fmaxf(h[(size_t)ym * WW + xl], h[(size_t)yp * WW + xl]));
        }
        if (x0 + 4 < WW) {
            int xr = x0 + 4;
            rm = fmaxf(h[(size_t)y * WW + xr], fmaxf(h[(size_t)ym * WW + xr], h[(size_t)yp * WW + xr]));
        }
        float pool0 = fmaxf(lm, fmaxf(m0, m1));
        float pool1 = fmaxf(m0, fmaxf(m1, m2));
        float pool2 = fmaxf(m1, fmaxf(m2, m3));
        float pool3 = fmaxf(m2, fmaxf(m3, rm));
        float p0 = (pool0 == a1.x) ? a1.x : 0.0f;
        float p1 = (pool1 == a1.y) ? a1.y : 0.0f;
        float p2 = (pool2 == a1.z) ? a1.z : 0.0f;
        float p3 = (pool3 == a1.w) ? a1.w : 0.0f;
        *(float4*)(pk + px) = make_float4(p0, p1, p2, p3);

        float pv[4] = {p0, p1, p2, p3};
        #pragma unroll
        for (int j = 0; j < 4; j++) {
            bool has = pv[j] > 0.0f;
            unsigned bal = __ballot_sync(0xffffffffu, has);
            if (bal) {
                int leader = __ffs(bal) - 1;
                int base = 0;
                if (lane == leader) base = atomicAdd(&s_cnt, __popc(bal));
                base = __shfl_sync(0xffffffffu, base, leader);
                if (has) {
                    int pos = base + __popc(bal & ((1u << lane) - 1u));
                    if (pos < CAP) { cv[pos] = pv[j]; ci[pos] = px + j; }
                }
            }
        }
    }
    __syncthreads();

    int cnt = s_cnt;
    bool candfast = (cnt >= TOPK) && (cnt <= CAP);

    if (candfast) {
        // histogram on value (uniform bins in [0,1))
        for (int i = tid; i < cnt; i += 1024) {
            int bin = (int)(cv[i] * (float)NBINS);
            bin = min(max(bin, 0), NBINS - 1);
            atomicAdd(&hist[bin], 1);
        }
        __syncthreads();
        if (tid == 0) {
            int cum = 0, bb = NBINS - 1;
            for (; bb >= 0; bb--) { cum += hist[bb]; if (cum >= TOPK) break; }
            s_bstar = bb;
            s_fast  = (cum <= MAXM) ? 1 : 0;
        }
        __syncthreads();
        if (s_fast) {
            int bstar = s_bstar;
            for (int i = tid; i < cnt; i += 1024) {
                float v = cv[i];
                int bin = (int)(v * (float)NBINS);
                bin = min(max(bin, 0), NBINS - 1);
                if (bin >= bstar) {
                    int pos = atomicAdd(&s_m, 1);
                    keys[pos] = ((unsigned long long)__float_as_uint(v) << 20)
                              | (unsigned)(HW - ci[i]);
                }
            }
        }
    } else {
        if (tid == 0) s_fast = 0;
    }
    __syncthreads();

    if (s_fast) {
        // warp 0: 32 argmax rounds over M (typically ~40-70) keys
        if (tid < 32) {
            int M = s_m;
            for (int r = 0; r < TOPK; r++) {
                unsigned long long bk = 0ull; int bp = -1;
                for (int i = lane; i < M; i += 32) {
                    unsigned long long k = keys[i];
                    if (k > bk) { bk = k; bp = i; }
                }
                #pragma unroll
                for (int o = 16; o; o >>= 1) {
                    unsigned long long k2 = __shfl_down_sync(0xffffffffu, bk, o);
                    int p2 = __shfl_down_sync(0xffffffffu, bp, o);
                    if (k2 > bk) { bk = k2; bp = p2; }
                }
                bk = __shfl_sync(0xffffffffu, bk, 0);
                bp = __shfl_sync(0xffffffffu, bp, 0);
                if (lane == 0) {
                    s_sc[r] = __uint_as_float((unsigned)(bk >> 20));
                    s_ix[r] = HW - (int)(bk & 0xFFFFFull);
                    keys[bp] = 0ull;
                }
                __syncwarp();
            }
        }
    } else {
        // robust fallback: block-wide argmax rounds over full peak map
        for (int r = 0; r < TOPK; r++) {
            float bv = -2.0f; int bi = 0x3fffffff;
            for (int i = tid; i < HW; i += 1024) {
                float v = pk[i];
                if (v > bv || (v == bv && i < bi)) { bv = v; bi = i; }
            }
            #pragma unroll
            for (int o = 16; o; o >>= 1) {
                float v2 = __shfl_down_sync(0xffffffffu, bv, o);
                int   i2 = __shfl_down_sync(0xffffffffu, bi, o);
                if (v2 > bv || (v2 == bv && i2 < bi)) { bv = v2; bi = i2; }
            }
            if (lane == 0) { rv[tid >> 5] = bv; rid[tid >> 5] = bi; }
            __syncthreads();
            if (tid < 32) {
                bv = rv[lane]; bi = rid[lane];
                #pragma unroll
                for (int o = 16; o; o >>= 1) {
                    float v2 = __shfl_down_sync(0xffffffffu, bv, o);
                    int   i2 = __shfl_down_sync(0xffffffffu, bi, o);
                    if (v2 > bv || (v2 == bv && i2 < bi)) { bv = v2; bi = i2; }
                }
                if (lane == 0) { s_sc[r] = bv; s_ix[r] = bi; pk[bi] = -1.0f; }
            }
            __syncthreads();
        }
    }
    __syncthreads();
    if (tid < TOPK) {
        g_scores[b * TOPK + tid] = s_sc[tid];
        g_idxs[b * TOPK + tid]   = s_ix[tid];
    }
}

// ============================================================
// Kernel 2: geometry — 64 blocks, 8 dets each; basis staged through
// shared in coalesced 51-row tiles (basis L2 traffic 33MB -> 4MB).
// ============================================================
#define DPB 8
#define TILE_R 51
__global__ void __launch_bounds__(256) geom_kernel(
    const float* __restrict__ pmaps,
    const float* __restrict__ oshapes,
    const float* __restrict__ pms,
    const float* __restrict__ u_base,
    const float* __restrict__ shp_base,
    const float* __restrict__ exp_base)
{
    int blk = blockIdx.x;
    int b   = blk >> 2;
    int g   = blk & 3;
    int tid = threadIdx.x;

    __shared__ float sp[DPB][92];
    __shared__ float s_shp[TILE_R * 50];
    __shared__ float s_exp[TILE_R * 29];
    __shared__ float sverts[DPB][204];
    __shared__ float slnm[DPB][NV * 2];
    __shared__ float s_sc[DPB];
    __shared__ int   s_ix[DPB];

    if (tid < DPB) {
        s_sc[tid] = g_scores[b * TOPK + g * DPB + tid];
        s_ix[tid] = g_idxs[b * TOPK + g * DPB + tid];
    }
    __syncthreads();

    // gather + denorm params
    for (int e = tid; e < DPB * 91; e += 256) {
        int det = e / 91, j = e - det * 91;
        sp[det][j] = fmaf(pmaps[((size_t)b * HW + (size_t)s_ix[det]) * 91 + j],
                          pms[91 + j], pms[j]);
    }
    __syncthreads();

    // verts via shared-staged basis tiles
    for (int t = 0; t < 4; t++) {
        int r0 = t * TILE_R;
        for (int i = tid; i < TILE_R * 50; i += 256) s_shp[i] = shp_base[(size_t)r0 * 50 + i];
        for (int i = tid; i < TILE_R * 29; i += 256) s_exp[i] = exp_base[(size_t)r0 * 29 + i];
        __syncthreads();
        for (int e = tid; e < DPB * TILE_R; e += 256) {
            int det = e & (DPB - 1);
            int r   = e >> 3;
            float a = u_base[r0 + r];
            const float* sb = &s_shp[r * 50];
            const float* cp = &sp[det][12];
            #pragma unroll
            for (int k = 0; k < 50; k++) a = fmaf(sb[k], cp[k], a);
            const float* eb = &s_exp[r * 29];
            const float* ce = &sp[det][62];
            #pragma unroll
            for (int k = 0; k < 29; k++) a = fmaf(eb[k], ce[k], a);
            sverts[det][r0 + r] = a;
        }
        __syncthreads();
    }

    // landmark projection
    for (int e = tid; e < DPB * NV; e += 256) {
        int det = e & (DPB - 1);
        int v   = e >> 3;
        float s  = sp[det][0];
        float vx = sverts[det][3 * v], vy = sverts[det][3 * v + 1], vz = sverts[det][3 * v + 2];
        float l0 = s * (vx * sp[det][1] + vy * sp[det][2] + vz * sp[det][3]);
        float l1 = s * (vx * sp[det][5] + vy * sp[det][6] + vz * sp[det][7]);
        int idx = s_ix[det];
        int ys = idx / WW, xs = idx - (idx / WW) * WW;
        float ry = oshapes[b * 2 + 0] / 160.0f;
        float rx = oshapes[b * 2 + 1] / 160.0f;
        float yy = l1 + (float)ys * ry;
        float xx = l0 + (float)xs * rx;
        slnm[det][2 * v]     = yy;
        slnm[det][2 * v + 1] = xx;
        size_t gdet = (size_t)(b * TOPK + g * DPB + det);
        g_lnmks[(gdet * NV + v) * 2 + 0] = yy;
        g_lnmks[(gdet * NV + v) * 2 + 1] = xx;
    }
    __syncthreads();

    // bbox min/max: one warp per det; pose on lane 0
    int w = tid >> 5, lane = tid & 31;
    {
        int det = w;
        float ymn = 1e30f, ymx = -1e30f, xmn = 1e30f, xmx = -1e30f;
        for (int v = lane; v < NV; v += 32) {
            float yy = slnm[det][2 * v], xx = slnm[det][2 * v + 1];
            ymn = fminf(ymn, yy); ymx = fmaxf(ymx, yy);
            xmn = fminf(xmn, xx); xmx = fmaxf(xmx, xx);
        }
        #pragma unroll
        for (int o = 16; o; o >>= 1) {
            ymn = fminf(ymn, __shfl_down_sync(0xffffffffu, ymn, o));
            ymx = fmaxf(ymx, __shfl_down_sync(0xffffffffu, ymx, o));
            xmn = fminf(xmn, __shfl_down_sync(0xffffffffu, xmn, o));
            xmx = fmaxf(xmx, __shfl_down_sync(0xffffffffu, xmx, o));
        }
        if (lane == 0) {
            size_t gdet = (size_t)(b * TOPK + g * DPB + det);
            bool mask = s_sc[det] > 0.5f;
            float* bb = g_bbox + gdet * 5;
            if (mask) { bb[0] = ymn; bb[1] = xmn; bb[2] = ymx; bb[3] = xmx; bb[4] = s_sc[det]; }
            else      { bb[0] = -1.0f; bb[1] = -1.0f; bb[2] = -1.0f; bb[3] = -1.0f; bb[4] = -1.0f; }

            float R20 = sp[det][9], R21 = sp[det][10], R22 = sp[det][11];
            float yaw   = asinf(-R20) * RAD2DEG;
            float cyw   = cosf(yaw);   // faithful: cos of yaw in DEGREES
            float pitch = atan2f(R21 / cyw, R22 / cyw) * RAD2DEG;
            float roll  = atan2f(sp[det][5] / cyw, sp[det][1] / cyw) * RAD2DEG;
            float* pp = g_pose + gdet * 3;
            pp[0] = pitch; pp[1] = yaw; pp[2] = roll;
        }
    }
}

// ============================================================
// Kernel 3: per-batch NMS + masking + output packing (unchanged R1)
// ============================================================
__global__ void __launch_bounds__(256) nms_kernel(float* __restrict__ out) {
    int b   = blockIdx.x;
    int tid = threadIdx.x;

    __shared__ float sbox[TOPK][4], sscore[TOPK];
    __shared__ float sob[TOPK][4],  sosc[TOPK];
    __shared__ int   svalid[TOPK],  smatch[TOPK];

    if (tid < TOPK) {
        const float* bb = g_bbox + ((size_t)b * TOPK + tid) * 5;
        #pragma unroll
        for (int c = 0; c < 4; c++) { sbox[tid][c] = bb[c]; sob[tid][c] = 0.0f; }
        sscore[tid] = bb[4];
        sosc[tid]   = 0.0f;
    }
    __syncthreads();

    if (tid < TOPK) {
        int lane = tid;
        float b0 = sbox[lane][0], b1 = sbox[lane][1], b2 = sbox[lane][2], b3 = sbox[lane][3];
        float area = (b2 - b0) * (b3 - b1);
        unsigned supp = 0u;
        for (int i = 0; i < TOPK; i++) {
            if (!((supp >> i) & 1u)) {
                float i0 = sbox[i][0], i1 = sbox[i][1], i2 = sbox[i][2], i3 = sbox[i][3];
                float ia = (i2 - i0) * (i3 - i1);
                float yy = fminf(b2, i2) - fmaxf(b0, i0);
                float xx = fminf(b3, i3) - fmaxf(b1, i1);
                float inter = fmaxf(yy, 0.0f) * fmaxf(xx, 0.0f);
                float uni   = area + ia - inter;
                float iou   = inter / fmaxf(uni, 1e-8f);
                bool  sup   = (iou > 0.4f) && (lane > i);
                supp |= __ballot_sync(0xffffffffu, sup);
            }
        }
        bool keep = !((supp >> lane) & 1u);
        unsigned km = __ballot_sync(0xffffffffu, keep);
        int rank = __popc(km & ((1u << lane) - 1u));
        if (keep) {
            sob[rank][0] = b0; sob[rank][1] = b1; sob[rank][2] = b2; sob[rank][3] = b3;
            sosc[rank]   = sscore[lane];
        }
    }
    __syncthreads();

    const float INF = __int_as_float(0x7f800000);

    if (tid < TOPK) {
        bool valid = true;
        #pragma unroll
        for (int c = 0; c < 4; c++) {
            float v = sob[tid][c];
            if (v == -1.0f || v == 0.0f) { v = INF; valid = false; }
            sob[tid][c] = v;
        }
        svalid[tid] = valid ? 1 : 0;
    }
    __syncthreads();

    if (tid < TOPK) {
        float sn = g_scores[b * TOPK + tid];
        int m = 0;
        for (int k = 0; k < TOPK; k++)
            if (svalid[k] && sosc[k] == sn) m = 1;
        smatch[tid] = m;
    }
    __syncthreads();

    float* ob = out + (size_t)b * TOPK * 6;
    for (int e = tid; e < TOPK * 6; e += 256) {
        int k = e / 6, c = e - k * 6;
        float v = (c < 4) ? sob[k][c] : ((c == 4) ? sosc[k] : 0.0f);
        ob[e] = v;
    }
    float* ol = out + (size_t)NB * TOPK * 6 + (size_t)b * TOPK * NV * 2;
    for (int e = tid; e < TOPK * NV * 2; e += 256) {
        int n = e / (NV * 2);
        float l = g_lnmks[(size_t)b * TOPK * NV * 2 + e];
        float v = (smatch[n] && l != -1.0f) ? l : INF;
        ol[e] = v;
    }
    float* op = out + (size_t)NB * TOPK * 6 + (size_t)NB * TOPK * NV * 2 + (size_t)b * TOPK * 3;
    for (int e = tid; e < TOPK * 3; e += 256) {
        int n = e / 3;
        float p = g_pose[(size_t)b * TOPK * 3 + e];
        float v = (smatch[n] && p != -1.0f) ? p : INF;
        op[e] = v;
    }
}

extern "C" void kernel_launch(void* const* d_in, const int* in_sizes, int n_in,
                              void* d_out, int out_size) {
    const float* hms      = (const float*)d_in[0];
    const float* pmaps    = (const float*)d_in[1];
    const float* oshapes  = (const float*)d_in[2];
    const float* pms      = (const float*)d_in[3];
    const float* u_base   = (const float*)d_in[4];
    const float* shp_base = (const float*)d_in[5];
    const float* exp_base = (const float*)d_in[6];
    float* out = (float*)d_out;

    topk_kernel<<<NB, 1024>>>(hms);
    geom_kernel<<<NB * 2 * DPB / 4, 256>>>(pmaps, oshapes, pms, u_base, shp_base, exp_base);
    nms_kernel<<<NB, 256>>>(out);
}